// round 1
// baseline (speedup 1.0000x reference)
#include <cuda_runtime.h>
#include <math.h>

// Problem constants
#define Bb 2
#define Tt 2048
#define Dd 2048
#define Nn 16
#define Kh 8
#define Hh 128
#define Mrows (Bb*Tt)          // 4096 total (b,t) rows
#define SOFTCAP 50.0f

// Scratch (no cudaMalloc allowed) — 96 MB total
__device__ float g_Q[(size_t)Mrows*Nn*Hh];   // [M, N*H] q after proj (+rope+scale)
__device__ float g_K[(size_t)Mrows*Kh*Hh];   // [M, K*H] k after proj (+rope)
__device__ float g_V[(size_t)Mrows*Kh*Hh];   // [M, K*H]
__device__ float g_E[(size_t)Mrows*Nn*Hh];   // encoded [M, N*H]

// ---------------------------------------------------------------------------
// Kernel 1: fused QKV projection.
// C[M=4096, J=4096] = X[M, D] @ Wcat[D, J], where J<2048 -> q heads,
// 2048..3071 -> k heads, 3072..4095 -> v heads. Column tile (128) == one head.
// ---------------------------------------------------------------------------
__global__ void proj_kernel(const float* __restrict__ x,
                            const float* __restrict__ w_q,
                            const float* __restrict__ w_kv) {
    __shared__ float As[16][132];   // As[kk][m] (transposed A tile)
    __shared__ float Bs[16][128];   // Bs[kk][j]

    const int jt = blockIdx.x;          // 0..31 (head slot)
    const int m0 = blockIdx.y * 128;
    const float* wsrc;
    float* dst;
    int dstride;
    if (jt < 16)      { wsrc = w_q  + (size_t)jt * Dd * Hh;       dst = g_Q + jt * Hh;       dstride = Nn * Hh; }
    else if (jt < 24) { wsrc = w_kv + (size_t)(jt-16) * Dd * Hh;  dst = g_K + (jt-16) * Hh;  dstride = Kh * Hh; }
    else              { wsrc = w_kv + (size_t)Kh*Dd*Hh + (size_t)(jt-24)*Dd*Hh;
                        dst = g_V + (jt-24) * Hh;                 dstride = Kh * Hh; }

    const int tid = threadIdx.x;        // 256 threads
    const int ty = tid >> 4, tx = tid & 15;

    float acc[8][8];
#pragma unroll
    for (int i = 0; i < 8; i++)
#pragma unroll
        for (int j = 0; j < 8; j++) acc[i][j] = 0.f;

    for (int k0 = 0; k0 < Dd; k0 += 16) {
        // Load A tile 128x16 (transposed into As[kk][m])
#pragma unroll
        for (int it = 0; it < 2; it++) {
            int idx = tid + it * 256;           // 0..511
            int r  = idx >> 2;                  // 0..127
            int c4 = (idx & 3) << 2;            // 0,4,8,12
            float4 v = *(const float4*)(x + (size_t)(m0 + r) * Dd + k0 + c4);
            As[c4+0][r] = v.x; As[c4+1][r] = v.y;
            As[c4+2][r] = v.z; As[c4+3][r] = v.w;
        }
        // Load B tile 16x128 (rows contiguous in memory)
#pragma unroll
        for (int it = 0; it < 2; it++) {
            int idx = tid + it * 256;
            int kk = idx >> 5;                  // 0..15
            int j4 = (idx & 31) << 2;           // 0..124
            *(float4*)(&Bs[kk][j4]) = *(const float4*)(wsrc + (size_t)(k0 + kk) * Hh + j4);
        }
        __syncthreads();
#pragma unroll
        for (int kk = 0; kk < 16; kk++) {
            float a[8], bfr[8];
#pragma unroll
            for (int i = 0; i < 8; i++) a[i] = As[kk][ty*8 + i];
#pragma unroll
            for (int j = 0; j < 8; j++) bfr[j] = Bs[kk][tx*8 + j];
#pragma unroll
            for (int i = 0; i < 8; i++)
#pragma unroll
                for (int j = 0; j < 8; j++)
                    acc[i][j] = fmaf(a[i], bfr[j], acc[i][j]);
        }
        __syncthreads();
    }
#pragma unroll
    for (int i = 0; i < 8; i++) {
        size_t m = (size_t)(m0 + ty*8 + i);
#pragma unroll
        for (int j = 0; j < 8; j++)
            dst[m * dstride + tx*8 + j] = acc[i][j];
    }
}

// ---------------------------------------------------------------------------
// Kernel 2: RoPE on Q (with 1/sqrt(H) scale) and K.
// ---------------------------------------------------------------------------
__global__ void rope_kernel(const int* __restrict__ positions) {
    const int totalQ = Mrows * Nn * 64;    // 4,194,304
    const int totalK = Mrows * Kh * 64;    // 2,097,152
    int idx = blockIdx.x * blockDim.x + threadIdx.x;
    if (idx < totalQ) {
        int m   = idx / (Nn * 64);
        int rem = idx % (Nn * 64);
        int n = rem >> 6;
        int i = rem & 63;
        float pos = (float)positions[m];
        float ts  = powf(10000.f, (2.f * i) / 128.f);
        float ang = pos / ts;
        float s, c;
        sincosf(ang, &s, &c);
        float* base = g_Q + (size_t)m * (Nn*Hh) + n * Hh;
        float f = base[i], sec = base[i + 64];
        const float sc = 0.08838834764831845f;   // 128^-0.5
        base[i]      = (f * c - sec * s) * sc;
        base[i + 64] = (sec * c + f * s) * sc;
    } else {
        int id2 = idx - totalQ;
        if (id2 >= totalK) return;
        int m   = id2 / (Kh * 64);
        int rem = id2 % (Kh * 64);
        int n = rem >> 6;
        int i = rem & 63;
        float pos = (float)positions[m];
        float ts  = powf(10000.f, (2.f * i) / 128.f);
        float ang = pos / ts;
        float s, c;
        sincosf(ang, &s, &c);
        float* base = g_K + (size_t)m * (Kh*Hh) + n * Hh;
        float f = base[i], sec = base[i + 64];
        base[i]      = f * c - sec * s;
        base[i + 64] = sec * c + f * s;
    }
}

// ---------------------------------------------------------------------------
// Kernel 3: causal attention with tanh softcap, 64q x 64k tiles.
// Softcap bounds logits to [-50, 50] -> fixed-max softmax p = exp(s - 50):
// no online max, no accumulator rescale.
// ---------------------------------------------------------------------------
#define SQ 129           // padded stride for Qs/Ks rows (bank spread, scalar reads)
#define SV 132           // padded stride for Vs (float4-aligned)
#define SP 65            // padded stride for P tile
#define ATTN_SMEM_FLOATS (64*SQ + 64*SQ + 64*SV + 64*SP + 64*17 + 64)
#define ATTN_SMEM_BYTES  (ATTN_SMEM_FLOATS * 4)

__global__ void attn_kernel() {
    extern __shared__ float sm[];
    float* Qs   = sm;                 // [64][SQ]
    float* Ks   = Qs   + 64*SQ;       // [64][SQ]
    float* Vs   = Ks   + 64*SQ;       // [64][SV]
    float* Ps   = Vs   + 64*SV;       // [64][SP]
    float* psum = Ps   + 64*SP;       // [64][17]
    float* Lsm  = psum + 64*17;       // [64]

    const int qt  = blockIdx.x;       // query tile 0..31
    const int n   = blockIdx.y;       // q head 0..15
    const int b   = blockIdx.z;
    const int kvh = n >> 1;           // G = 2
    const int tid = threadIdx.x;      // 256
    const int ty  = tid >> 4, tx = tid & 15;
    const int r0  = ty * 4;           // S rows (also O rows)
    const int c0s = tx * 4;           // S cols
    const int c0o = tx * 8;           // O cols

    // Load Q tile [64][128]
#pragma unroll
    for (int it = 0; it < 8; it++) {
        int idx = tid + it * 256;           // 0..2047
        int r = idx >> 5;
        int h = (idx & 31) << 2;
        float4 v = *(const float4*)(g_Q + ((size_t)(b*Tt + qt*64 + r) * Nn + n) * Hh + h);
        Qs[r*SQ + h]     = v.x;
        Qs[r*SQ + h + 1] = v.y;
        Qs[r*SQ + h + 2] = v.z;
        Qs[r*SQ + h + 3] = v.w;
    }
    if (tid < 64) Lsm[tid] = 0.f;

    float O[4][8];
#pragma unroll
    for (int i = 0; i < 4; i++)
#pragma unroll
        for (int j = 0; j < 8; j++) O[i][j] = 0.f;

    __syncthreads();

    const float inv_cap = 1.0f / SOFTCAP;
    for (int st = 0; st <= qt; st++) {
        // Load K and V tiles [64][128]
#pragma unroll
        for (int it = 0; it < 8; it++) {
            int idx = tid + it * 256;
            int r = idx >> 5;
            int h = (idx & 31) << 2;
            size_t gro = ((size_t)(b*Tt + st*64 + r) * Kh + kvh) * Hh + h;
            float4 kv = *(const float4*)(g_K + gro);
            Ks[r*SQ + h]     = kv.x;
            Ks[r*SQ + h + 1] = kv.y;
            Ks[r*SQ + h + 2] = kv.z;
            Ks[r*SQ + h + 3] = kv.w;
            *(float4*)(Vs + r*SV + h) = *(const float4*)(g_V + gro);
        }
        __syncthreads();

        // S = Q K^T   (4x4 per thread)
        float s[4][4];
#pragma unroll
        for (int i = 0; i < 4; i++)
#pragma unroll
            for (int j = 0; j < 4; j++) s[i][j] = 0.f;
#pragma unroll 4
        for (int kk = 0; kk < 128; kk++) {
            float a[4], bb[4];
#pragma unroll
            for (int i = 0; i < 4; i++) a[i]  = Qs[(r0  + i)*SQ + kk];
#pragma unroll
            for (int j = 0; j < 4; j++) bb[j] = Ks[(c0s + j)*SQ + kk];
#pragma unroll
            for (int i = 0; i < 4; i++)
#pragma unroll
                for (int j = 0; j < 4; j++)
                    s[i][j] = fmaf(a[i], bb[j], s[i][j]);
        }

        // softcap + causal mask + exp(s-50); write P and row partial sums
        const bool diag = (st == qt);
        float rsum[4] = {0.f, 0.f, 0.f, 0.f};
#pragma unroll
        for (int i = 0; i < 4; i++) {
#pragma unroll
            for (int j = 0; j < 4; j++) {
                float v = tanhf(s[i][j] * inv_cap) * SOFTCAP;
                float p = (diag && (c0s + j > r0 + i)) ? 0.f : expf(v - SOFTCAP);
                Ps[(r0 + i)*SP + c0s + j] = p;
                rsum[i] += p;
            }
            psum[(r0 + i)*17 + tx] = rsum[i];
        }
        __syncthreads();

        if (tid < 64) {
            float a = 0.f;
#pragma unroll
            for (int xx = 0; xx < 16; xx++) a += psum[tid*17 + xx];
            Lsm[tid] += a;
        }

        // O += P @ V   (4 rows x 8 cols per thread)
#pragma unroll 2
        for (int ss = 0; ss < 64; ss++) {
            float p[4];
#pragma unroll
            for (int i = 0; i < 4; i++) p[i] = Ps[(r0 + i)*SP + ss];
            float4 v0 = *(const float4*)(Vs + ss*SV + c0o);
            float4 v1 = *(const float4*)(Vs + ss*SV + c0o + 4);
#pragma unroll
            for (int i = 0; i < 4; i++) {
                O[i][0] = fmaf(p[i], v0.x, O[i][0]);
                O[i][1] = fmaf(p[i], v0.y, O[i][1]);
                O[i][2] = fmaf(p[i], v0.z, O[i][2]);
                O[i][3] = fmaf(p[i], v0.w, O[i][3]);
                O[i][4] = fmaf(p[i], v1.x, O[i][4]);
                O[i][5] = fmaf(p[i], v1.y, O[i][5]);
                O[i][6] = fmaf(p[i], v1.z, O[i][6]);
                O[i][7] = fmaf(p[i], v1.w, O[i][7]);
            }
        }
        __syncthreads();
    }

    // Normalize and write encoded
#pragma unroll
    for (int i = 0; i < 4; i++) {
        float inv = 1.f / Lsm[r0 + i];
        size_t o = ((size_t)(b*Tt + qt*64 + r0 + i) * Nn + n) * Hh + c0o;
#pragma unroll
        for (int j = 0; j < 8; j++)
            g_E[o + j] = O[i][j] * inv;
    }
}

// ---------------------------------------------------------------------------
// Kernel 4: output projection. out[M, D] = E[M, 2048] @ Wout[2048, D].
// w_out [N,H,D] row-major == [2048, 2048] with row index n*H+h. Exact match.
// ---------------------------------------------------------------------------
__global__ void outproj_kernel(const float* __restrict__ w_out,
                               float* __restrict__ out) {
    __shared__ float As[16][132];
    __shared__ float Bs[16][128];

    const int j0 = blockIdx.x * 128;
    const int m0 = blockIdx.y * 128;
    const int tid = threadIdx.x;
    const int ty = tid >> 4, tx = tid & 15;

    float acc[8][8];
#pragma unroll
    for (int i = 0; i < 8; i++)
#pragma unroll
        for (int j = 0; j < 8; j++) acc[i][j] = 0.f;

    for (int k0 = 0; k0 < Nn*Hh; k0 += 16) {
#pragma unroll
        for (int it = 0; it < 2; it++) {
            int idx = tid + it * 256;
            int r  = idx >> 2;
            int c4 = (idx & 3) << 2;
            float4 v = *(const float4*)(g_E + (size_t)(m0 + r) * (Nn*Hh) + k0 + c4);
            As[c4+0][r] = v.x; As[c4+1][r] = v.y;
            As[c4+2][r] = v.z; As[c4+3][r] = v.w;
        }
#pragma unroll
        for (int it = 0; it < 2; it++) {
            int idx = tid + it * 256;
            int kk = idx >> 5;
            int j4 = (idx & 31) << 2;
            *(float4*)(&Bs[kk][j4]) = *(const float4*)(w_out + (size_t)(k0 + kk) * Dd + j0 + j4);
        }
        __syncthreads();
#pragma unroll
        for (int kk = 0; kk < 16; kk++) {
            float a[8], bfr[8];
#pragma unroll
            for (int i = 0; i < 8; i++) a[i] = As[kk][ty*8 + i];
#pragma unroll
            for (int j = 0; j < 8; j++) bfr[j] = Bs[kk][tx*8 + j];
#pragma unroll
            for (int i = 0; i < 8; i++)
#pragma unroll
                for (int j = 0; j < 8; j++)
                    acc[i][j] = fmaf(a[i], bfr[j], acc[i][j]);
        }
        __syncthreads();
    }
#pragma unroll
    for (int i = 0; i < 8; i++) {
        size_t m = (size_t)(m0 + ty*8 + i);
#pragma unroll
        for (int j = 0; j < 8; j++)
            out[m * Dd + j0 + tx*8 + j] = acc[i][j];
    }
}

// ---------------------------------------------------------------------------
extern "C" void kernel_launch(void* const* d_in, const int* in_sizes, int n_in,
                              void* d_out, int out_size) {
    const float* x     = (const float*)d_in[0];
    const int*   pos   = (const int*)  d_in[1];
    // d_in[2] = attn_mask (causal tril; handled analytically, unused)
    const float* w_q   = (const float*)d_in[3];
    const float* w_kv  = (const float*)d_in[4];
    const float* w_out = (const float*)d_in[5];
    float* out = (float*)d_out;

    // 1) QKV projection
    proj_kernel<<<dim3(32, 32), 256>>>(x, w_q, w_kv);

    // 2) RoPE (Q scaled, K unscaled)
    {
        int total = Mrows*Nn*64 + Mrows*Kh*64;   // 6,291,456
        rope_kernel<<<(total + 255) / 256, 256>>>(pos);
    }

    // 3) Attention
    cudaFuncSetAttribute(attn_kernel,
                         cudaFuncAttributeMaxDynamicSharedMemorySize,
                         ATTN_SMEM_BYTES);
    attn_kernel<<<dim3(32, 16, 2), 256, ATTN_SMEM_BYTES>>>();

    // 4) Output projection
    outproj_kernel<<<dim3(16, 32), 256>>>(w_out, out);
}

// round 5
// speedup vs baseline: 3.1318x; 3.1318x over previous
#include <cuda_runtime.h>
#include <math.h>
#include <stdint.h>

// Problem constants
#define Bb 2
#define Tt 2048
#define Dd 2048
#define Nn 16
#define Kh 8
#define Hh 128
#define Mrows (Bb*Tt)
#define SOFTCAP 50.0f

// Scratch (no cudaMalloc allowed)
__device__ int   g_fastok;                     // 1 if cp.async + tf32 mma fragment contract verified
__device__ float g_X32[(size_t)Mrows*Dd];      // x rounded to tf32
__device__ float g_Q[(size_t)Mrows*Nn*Hh];     // [M, 2048]
__device__ float g_K[(size_t)Mrows*Kh*Hh];     // [M, 1024]
__device__ float g_V[(size_t)Mrows*Kh*Hh];     // [M, 1024]
__device__ float g_E[(size_t)Mrows*Nn*Hh];     // encoded
__device__ float g_Wt[(size_t)4096*2048];      // W_qkv^T (tf32)
__device__ float g_Wot[(size_t)2048*2048];     // w_out^T (tf32)

// ---------------------------------------------------------------------------
// Helpers
// ---------------------------------------------------------------------------
__device__ __forceinline__ uint32_t smem_to_u32(const void* p) {
    uint32_t a;
    asm("{ .reg .u64 t; cvta.to.shared.u64 t, %1; cvt.u32.u64 %0, t; }" : "=r"(a) : "l"(p));
    return a;
}
__device__ __forceinline__ float to_tf32(float x) {
    float r;
    asm("cvt.rna.tf32.f32 %0, %1;" : "=f"(r) : "f"(x));
    return r;
}
__device__ __forceinline__ void mma_tf32(float d[4], const uint32_t a[4], const uint32_t b[2]) {
    asm volatile(
        "mma.sync.aligned.m16n8k8.row.col.f32.tf32.tf32.f32 "
        "{%0,%1,%2,%3}, {%4,%5,%6,%7}, {%8,%9}, {%0,%1,%2,%3};"
        : "+f"(d[0]), "+f"(d[1]), "+f"(d[2]), "+f"(d[3])
        : "r"(a[0]), "r"(a[1]), "r"(a[2]), "r"(a[3]), "r"(b[0]), "r"(b[1]));
}
#define CP_ASYNC16(dst, src) \
    asm volatile("cp.async.cg.shared.global [%0], [%1], 16;" :: "r"(dst), "l"(src) : "memory")
#define CP_COMMIT() asm volatile("cp.async.commit_group;" ::: "memory")
#define CP_WAIT1()  asm volatile("cp.async.wait_group 1;" ::: "memory")
#define CP_WAIT0()  asm volatile("cp.async.wait_group 0;" ::: "memory")
#define FU(x) __float_as_uint(x)

// ---------------------------------------------------------------------------
// Probe: verify cp.async AND the full m16n8k8 tf32 fragment contract.
// A[16][8], B[8][8] with distinct small ints (exact in tf32); compare D
// against in-kernel scalar reference at the exact positions my kernels assume.
// ---------------------------------------------------------------------------
__global__ void probe_kernel(const float* __restrict__ x) {
    __shared__ float buf[128];
    __shared__ float A[16][8];
    __shared__ float B[8][8];
    const int lane = threadIdx.x;   // 32 threads
    // cp.async roundtrip
    uint32_t dst = smem_to_u32(buf) + lane * 16;
    CP_ASYNC16(dst, x + lane * 4);
    CP_COMMIT(); CP_WAIT0();
    __syncwarp();
    bool good = true;
#pragma unroll
    for (int i = 0; i < 4; i++) good &= (buf[lane*4 + i] == x[lane*4 + i]);
    // fill A, B
    for (int i = lane; i < 128; i += 32) A[i >> 3][i & 7] = (float)((i * 5) % 13 - 6);
    for (int i = lane; i < 64;  i += 32) B[i >> 3][i & 7] = (float)((i * 3) % 7  - 3);
    __syncwarp();
    const int g = lane >> 2, t4 = lane & 3;
    uint32_t a[4] = {FU(A[g][t4]), FU(A[g+8][t4]), FU(A[g][t4+4]), FU(A[g+8][t4+4])};
    uint32_t b[2] = {FU(B[t4][g]), FU(B[t4+4][g])};
    float d[4] = {0.f, 0.f, 0.f, 0.f};
    mma_tf32(d, a, b);
    // reference positions: d0=D[g][2t4], d1=D[g][2t4+1], d2=D[g+8][2t4], d3=D[g+8][2t4+1]
    int rows[2] = {g, g + 8};
    int cols[2] = {2*t4, 2*t4 + 1};
#pragma unroll
    for (int ri = 0; ri < 2; ri++)
#pragma unroll
        for (int ci = 0; ci < 2; ci++) {
            float ref = 0.f;
#pragma unroll
            for (int k = 0; k < 8; k++) ref += A[rows[ri]][k] * B[k][cols[ci]];
            good &= (d[ri*2 + ci] == ref);
        }
    unsigned m = __ballot_sync(0xffffffffu, good);
    if (lane == 0) g_fastok = (m == 0xffffffffu) ? 1 : 0;
}

// ---------------------------------------------------------------------------
// Prep kernels (unconditional)
// ---------------------------------------------------------------------------
__global__ void roundx_kernel(const float* __restrict__ x) {
    size_t i = ((size_t)blockIdx.x * blockDim.x + threadIdx.x) * 4;
    float4 v = *(const float4*)(x + i);
    v.x = to_tf32(v.x); v.y = to_tf32(v.y); v.z = to_tf32(v.z); v.w = to_tf32(v.w);
    *(float4*)(g_X32 + i) = v;
}

__global__ void transpose_kernel(const float* __restrict__ w_q,
                                 const float* __restrict__ w_kv,
                                 const float* __restrict__ w_out) {
    __shared__ float t[32][33];
    const int tx = threadIdx.x, ty = threadIdx.y;   // 32 x 8
    const int bx = blockIdx.x, by = blockIdx.y;
    if (blockIdx.z == 0) {
        const int j0 = by * 32, d0 = bx * 32;
        const int j = j0 + tx;
        const int h = j & 127, hd = j >> 7;
        const float* src;
        if (hd < 16)      src = w_q  + (size_t)hd * 2048 * 128 + h;
        else if (hd < 24) src = w_kv + (size_t)(hd - 16) * 2048 * 128 + h;
        else              src = w_kv + (size_t)8 * 2048 * 128 + (size_t)(hd - 24) * 2048 * 128 + h;
#pragma unroll
        for (int i = 0; i < 4; i++) {
            int d = d0 + ty + i * 8;
            t[tx][ty + i * 8] = to_tf32(src[(size_t)d * 128]);   // t[j_loc][d_loc]
        }
        __syncthreads();
#pragma unroll
        for (int i = 0; i < 4; i++) {
            int jj = j0 + ty + i * 8;
            g_Wt[(size_t)jj * 2048 + d0 + tx] = t[ty + i * 8][tx];
        }
    } else {
        if (by >= 64) return;
        const int k0 = by * 32, d0 = bx * 32;
#pragma unroll
        for (int i = 0; i < 4; i++) {
            int k = k0 + ty + i * 8;
            t[ty + i * 8][tx] = to_tf32(w_out[(size_t)k * 2048 + d0 + tx]);  // t[k_loc][d_loc]
        }
        __syncthreads();
#pragma unroll
        for (int i = 0; i < 4; i++) {
            int d = d0 + ty + i * 8;
            g_Wot[(size_t)d * 2048 + k0 + tx] = t[tx][ty + i * 8];
        }
    }
}

// ---------------------------------------------------------------------------
// FAST PATH GEMM: tf32 mma, CTA 128x256, warp 64x64, K-chunk 32, 2-stage cp.async.
// Operand pointers selected IN DEVICE CODE (host cannot pass __device__ symbols).
//   mode 0: C = g_X32 @ g_Wt^T  -> split g_Q/g_K/g_V
//   mode 1: C = g_E  @ g_Wot^T  -> outp
// ---------------------------------------------------------------------------
#define GP 36
#define STAGE_FLOATS (128*GP + 256*GP)
#define GEMM_SMEM (2*STAGE_FLOATS*4)

__global__ __launch_bounds__(256, 1)
void gemm_mma_kernel(float* __restrict__ outp, int mode) {
    if (g_fastok != 1) return;
    const float* A  = (mode == 0) ? g_X32 : g_E;
    const float* Bt = (mode == 0) ? g_Wt  : g_Wot;
    extern __shared__ float smf[];
    const uint32_t smem_base = smem_to_u32(smf);
    const int tid = threadIdx.x;
    const int lane = tid & 31;
    const int wid = tid >> 5;
    const int g = lane >> 2, t4 = lane & 3;
    const int wm = wid & 1, wn = wid >> 1;
    const int m0 = blockIdx.y * 128;
    const int jg = blockIdx.x * 256;

    float c[4][8][4];
#pragma unroll
    for (int mt = 0; mt < 4; mt++)
#pragma unroll
        for (int nt = 0; nt < 8; nt++)
#pragma unroll
            for (int q = 0; q < 4; q++) c[mt][nt][q] = 0.f;

    auto issue = [&](int kt, int stage) {
        const int k0 = kt * 32;
        const uint32_t sbA = smem_base + stage * (STAGE_FLOATS * 4);
        const uint32_t sbB = sbA + 128 * GP * 4;
#pragma unroll
        for (int i = 0; i < 4; i++) {
            int ch = tid + i * 256;
            int r = ch >> 3, cc = (ch & 7) << 2;
            CP_ASYNC16(sbA + (uint32_t)(r * GP + cc) * 4,
                       A + (size_t)(m0 + r) * 2048 + k0 + cc);
        }
#pragma unroll
        for (int i = 0; i < 8; i++) {
            int ch = tid + i * 256;
            int r = ch >> 3, cc = (ch & 7) << 2;
            CP_ASYNC16(sbB + (uint32_t)(r * GP + cc) * 4,
                       Bt + (size_t)(jg + r) * 2048 + k0 + cc);
        }
    };

    issue(0, 0);
    CP_COMMIT();

    for (int kt = 0; kt < 64; kt++) {
        if (kt < 63) { issue(kt + 1, (kt + 1) & 1); CP_COMMIT(); CP_WAIT1(); }
        else         { CP_WAIT0(); }
        __syncthreads();
        const float* as = smf + (kt & 1) * STAGE_FLOATS;
        const float* bs = as + 128 * GP;
#pragma unroll
        for (int ks = 0; ks < 4; ks++) {
            const int k = ks * 8;
            uint32_t a[4][4];
#pragma unroll
            for (int mt = 0; mt < 4; mt++) {
                const float* ap = as + (wm * 64 + mt * 16 + g) * GP + k + t4;
                a[mt][0] = FU(ap[0]);
                a[mt][1] = FU(ap[8 * GP]);
                a[mt][2] = FU(ap[4]);
                a[mt][3] = FU(ap[8 * GP + 4]);
            }
#pragma unroll
            for (int nt = 0; nt < 8; nt++) {
                const float* bp = bs + (wn * 64 + nt * 8 + g) * GP + k + t4;
                uint32_t b[2] = {FU(bp[0]), FU(bp[4])};
#pragma unroll
                for (int mt = 0; mt < 4; mt++)
                    mma_tf32(c[mt][nt], a[mt], b);
            }
        }
        __syncthreads();
    }

    float* obase; int ostride;
    if (mode == 0) {
        if (jg < 2048)      { obase = g_Q + jg;        ostride = 2048; }
        else if (jg < 3072) { obase = g_K + (jg-2048); ostride = 1024; }
        else                { obase = g_V + (jg-3072); ostride = 1024; }
    } else { obase = outp + jg; ostride = 2048; }
#pragma unroll
    for (int mt = 0; mt < 4; mt++) {
        int r0 = m0 + wm * 64 + mt * 16 + g;
#pragma unroll
        for (int nt = 0; nt < 8; nt++) {
            int col = wn * 64 + nt * 8 + 2 * t4;
            *(float2*)(obase + (size_t)r0 * ostride + col) =
                make_float2(c[mt][nt][0], c[mt][nt][1]);
            *(float2*)(obase + (size_t)(r0 + 8) * ostride + col) =
                make_float2(c[mt][nt][2], c[mt][nt][3]);
        }
    }
}

// ---------------------------------------------------------------------------
// SLOW PATH (round-1 FFMA, proven) — runs only if probe failed
// ---------------------------------------------------------------------------
__global__ void proj_slow(const float* __restrict__ x,
                          const float* __restrict__ w_q,
                          const float* __restrict__ w_kv) {
    if (g_fastok == 1) return;
    __shared__ float As[16][132];
    __shared__ float Bs[16][128];
    const int jt = blockIdx.x;
    const int m0 = blockIdx.y * 128;
    const float* wsrc;
    float* dst;
    int dstride;
    if (jt < 16)      { wsrc = w_q  + (size_t)jt * Dd * Hh;       dst = g_Q + jt * Hh;       dstride = Nn * Hh; }
    else if (jt < 24) { wsrc = w_kv + (size_t)(jt-16) * Dd * Hh;  dst = g_K + (jt-16) * Hh;  dstride = Kh * Hh; }
    else              { wsrc = w_kv + (size_t)Kh*Dd*Hh + (size_t)(jt-24)*Dd*Hh;
                        dst = g_V + (jt-24) * Hh;                 dstride = Kh * Hh; }
    const int tid = threadIdx.x;
    const int ty = tid >> 4, tx = tid & 15;
    float acc[8][8];
#pragma unroll
    for (int i = 0; i < 8; i++)
#pragma unroll
        for (int j = 0; j < 8; j++) acc[i][j] = 0.f;
    for (int k0 = 0; k0 < Dd; k0 += 16) {
#pragma unroll
        for (int it = 0; it < 2; it++) {
            int idx = tid + it * 256;
            int r  = idx >> 2;
            int c4 = (idx & 3) << 2;
            float4 v = *(const float4*)(x + (size_t)(m0 + r) * Dd + k0 + c4);
            As[c4+0][r] = v.x; As[c4+1][r] = v.y;
            As[c4+2][r] = v.z; As[c4+3][r] = v.w;
        }
#pragma unroll
        for (int it = 0; it < 2; it++) {
            int idx = tid + it * 256;
            int kk = idx >> 5;
            int j4 = (idx & 31) << 2;
            *(float4*)(&Bs[kk][j4]) = *(const float4*)(wsrc + (size_t)(k0 + kk) * Hh + j4);
        }
        __syncthreads();
#pragma unroll
        for (int kk = 0; kk < 16; kk++) {
            float a[8], bfr[8];
#pragma unroll
            for (int i = 0; i < 8; i++) a[i] = As[kk][ty*8 + i];
#pragma unroll
            for (int j = 0; j < 8; j++) bfr[j] = Bs[kk][tx*8 + j];
#pragma unroll
            for (int i = 0; i < 8; i++)
#pragma unroll
                for (int j = 0; j < 8; j++)
                    acc[i][j] = fmaf(a[i], bfr[j], acc[i][j]);
        }
        __syncthreads();
    }
#pragma unroll
    for (int i = 0; i < 8; i++) {
        size_t m = (size_t)(m0 + ty*8 + i);
#pragma unroll
        for (int j = 0; j < 8; j++)
            dst[m * dstride + tx*8 + j] = acc[i][j];
    }
}

__global__ void rope_kernel(const int* __restrict__ positions) {
    const int totalQ = Mrows * Nn * 64;
    const int totalK = Mrows * Kh * 64;
    int idx = blockIdx.x * blockDim.x + threadIdx.x;
    if (idx < totalQ) {
        int m   = idx / (Nn * 64);
        int rem = idx % (Nn * 64);
        int n = rem >> 6;
        int i = rem & 63;
        float pos = (float)positions[m];
        float ts  = powf(10000.f, (2.f * i) / 128.f);
        float s, c;
        sincosf(pos / ts, &s, &c);
        float* base = g_Q + (size_t)m * (Nn*Hh) + n * Hh;
        float f = base[i], sec = base[i + 64];
        const float sc = 0.08838834764831845f;
        base[i]      = (f * c - sec * s) * sc;
        base[i + 64] = (sec * c + f * s) * sc;
    } else {
        int id2 = idx - totalQ;
        if (id2 >= totalK) return;
        int m   = id2 / (Kh * 64);
        int rem = id2 % (Kh * 64);
        int n = rem >> 6;
        int i = rem & 63;
        float pos = (float)positions[m];
        float ts  = powf(10000.f, (2.f * i) / 128.f);
        float s, c;
        sincosf(pos / ts, &s, &c);
        float* base = g_K + (size_t)m * (Kh*Hh) + n * Hh;
        float f = base[i], sec = base[i + 64];
        base[i]      = f * c - sec * s;
        base[i + 64] = sec * c + f * s;
    }
}

// FAST attention (mma tf32)
#define AQ 132
#define AP 68
#define ATTN_FLOATS (3*64*AQ + 64*AP + 128 + 64)
#define ATTN_SMEM_F (ATTN_FLOATS * 4)

__global__ __launch_bounds__(256, 1)
void attn_fast() {
    if (g_fastok != 1) return;
    extern __shared__ float sm[];
    float* Qs   = sm;
    float* Ks   = Qs + 64*AQ;
    float* Vs   = Ks + 64*AQ;
    float* Ps   = Vs + 64*AQ;
    float* psum = Ps + 64*AP;
    float* Lsm  = psum + 128;

    const int qt = blockIdx.x, n = blockIdx.y, b = blockIdx.z;
    const int kvh = n >> 1;
    const int tid = threadIdx.x, lane = tid & 31, wid = tid >> 5;
    const int g = lane >> 2, t4 = lane & 3;
    const int wm = wid & 3, wn = wid >> 2;
    const int rb = wm * 16;

#pragma unroll
    for (int it = 0; it < 8; it++) {
        int idx = tid + it * 256;
        int r = idx >> 5, h = (idx & 31) << 2;
        float4 v = *(const float4*)(g_Q + ((size_t)(b*Tt + qt*64 + r) * Nn + n) * Hh + h);
        v.x = to_tf32(v.x); v.y = to_tf32(v.y); v.z = to_tf32(v.z); v.w = to_tf32(v.w);
        *(float4*)(Qs + r*AQ + h) = v;
    }
    if (tid < 64) Lsm[tid] = 0.f;

    float o[8][4];
#pragma unroll
    for (int nt = 0; nt < 8; nt++)
#pragma unroll
        for (int q = 0; q < 4; q++) o[nt][q] = 0.f;

    __syncthreads();

    for (int st = 0; st <= qt; st++) {
#pragma unroll
        for (int it = 0; it < 8; it++) {
            int idx = tid + it * 256;
            int r = idx >> 5, h = (idx & 31) << 2;
            size_t gro = ((size_t)(b*Tt + st*64 + r) * Kh + kvh) * Hh + h;
            float4 kv = *(const float4*)(g_K + gro);
            kv.x = to_tf32(kv.x); kv.y = to_tf32(kv.y); kv.z = to_tf32(kv.z); kv.w = to_tf32(kv.w);
            *(float4*)(Ks + r*AQ + h) = kv;
            float4 vv = *(const float4*)(g_V + gro);
            vv.x = to_tf32(vv.x); vv.y = to_tf32(vv.y); vv.z = to_tf32(vv.z); vv.w = to_tf32(vv.w);
            *(float4*)(Vs + r*AQ + h) = vv;
        }
        __syncthreads();

        float s[4][4];
#pragma unroll
        for (int nt = 0; nt < 4; nt++)
#pragma unroll
            for (int q = 0; q < 4; q++) s[nt][q] = 0.f;
#pragma unroll
        for (int ks = 0; ks < 16; ks++) {
            const int k = ks * 8;
            const float* ap = Qs + (rb + g) * AQ + k + t4;
            uint32_t a[4] = {FU(ap[0]), FU(ap[8*AQ]), FU(ap[4]), FU(ap[8*AQ + 4])};
#pragma unroll
            for (int nt = 0; nt < 4; nt++) {
                const float* bp = Ks + (wn*32 + nt*8 + g) * AQ + k + t4;
                uint32_t bb[2] = {FU(bp[0]), FU(bp[4])};
                mma_tf32(s[nt], a, bb);
            }
        }

        const bool diag = (st == qt);
        const int rlo = rb + g, rhi = rb + g + 8;
        float rs0 = 0.f, rs1 = 0.f;
#pragma unroll
        for (int nt = 0; nt < 4; nt++) {
            int cc = wn*32 + nt*8 + 2*t4;
            float p00 = expf(tanhf(s[nt][0] * (1.f/SOFTCAP)) * SOFTCAP - SOFTCAP);
            float p01 = expf(tanhf(s[nt][1] * (1.f/SOFTCAP)) * SOFTCAP - SOFTCAP);
            float p10 = expf(tanhf(s[nt][2] * (1.f/SOFTCAP)) * SOFTCAP - SOFTCAP);
            float p11 = expf(tanhf(s[nt][3] * (1.f/SOFTCAP)) * SOFTCAP - SOFTCAP);
            if (diag) {
                if (cc     > rlo) p00 = 0.f;
                if (cc + 1 > rlo) p01 = 0.f;
                if (cc     > rhi) p10 = 0.f;
                if (cc + 1 > rhi) p11 = 0.f;
            }
            p00 = to_tf32(p00); p01 = to_tf32(p01);
            p10 = to_tf32(p10); p11 = to_tf32(p11);
            *(float2*)(Ps + rlo*AP + cc) = make_float2(p00, p01);
            *(float2*)(Ps + rhi*AP + cc) = make_float2(p10, p11);
            rs0 += p00 + p01;
            rs1 += p10 + p11;
        }
        rs0 += __shfl_xor_sync(0xffffffffu, rs0, 1);
        rs0 += __shfl_xor_sync(0xffffffffu, rs0, 2);
        rs1 += __shfl_xor_sync(0xffffffffu, rs1, 1);
        rs1 += __shfl_xor_sync(0xffffffffu, rs1, 2);
        if (t4 == 0) {
            psum[rlo*2 + wn] = rs0;
            psum[rhi*2 + wn] = rs1;
        }
        __syncthreads();
        if (tid < 64) Lsm[tid] += psum[tid*2] + psum[tid*2 + 1];

#pragma unroll
        for (int ks = 0; ks < 8; ks++) {
            const int k = ks * 8;
            const float* ap = Ps + (rb + g) * AP + k + t4;
            uint32_t a[4] = {FU(ap[0]), FU(ap[8*AP]), FU(ap[4]), FU(ap[8*AP + 4])};
#pragma unroll
            for (int nt = 0; nt < 8; nt++) {
                const float* bp = Vs + (k + t4) * AQ + wn*64 + nt*8 + g;
                uint32_t bb[2] = {FU(bp[0]), FU(bp[4*AQ])};
                mma_tf32(o[nt], a, bb);
            }
        }
        __syncthreads();
    }

    const int rlo = rb + g, rhi = rb + g + 8;
    const float invlo = 1.f / Lsm[rlo];
    const float invhi = 1.f / Lsm[rhi];
#pragma unroll
    for (int nt = 0; nt < 8; nt++) {
        int col = wn*64 + nt*8 + 2*t4;
        size_t olo = ((size_t)(b*Tt + qt*64 + rlo) * Nn + n) * Hh + col;
        size_t ohi = ((size_t)(b*Tt + qt*64 + rhi) * Nn + n) * Hh + col;
        *(float2*)(g_E + olo) = make_float2(to_tf32(o[nt][0]*invlo), to_tf32(o[nt][1]*invlo));
        *(float2*)(g_E + ohi) = make_float2(to_tf32(o[nt][2]*invhi), to_tf32(o[nt][3]*invhi));
    }
}

// SLOW attention (round-1 FFMA)
#define SQ 129
#define SV 132
#define SP 65
#define ATTN_SLOW_FLOATS (64*SQ + 64*SQ + 64*SV + 64*SP + 64*17 + 64)
#define ATTN_SMEM_S (ATTN_SLOW_FLOATS * 4)

__global__ void attn_slow() {
    if (g_fastok == 1) return;
    extern __shared__ float sm[];
    float* Qs   = sm;
    float* Ks   = Qs   + 64*SQ;
    float* Vs   = Ks   + 64*SQ;
    float* Ps   = Vs   + 64*SV;
    float* psum = Ps   + 64*SP;
    float* Lsm  = psum + 64*17;

    const int qt  = blockIdx.x;
    const int n   = blockIdx.y;
    const int b   = blockIdx.z;
    const int kvh = n >> 1;
    const int tid = threadIdx.x;
    const int ty  = tid >> 4, tx = tid & 15;
    const int r0  = ty * 4;
    const int c0s = tx * 4;
    const int c0o = tx * 8;

#pragma unroll
    for (int it = 0; it < 8; it++) {
        int idx = tid + it * 256;
        int r = idx >> 5;
        int h = (idx & 31) << 2;
        float4 v = *(const float4*)(g_Q + ((size_t)(b*Tt + qt*64 + r) * Nn + n) * Hh + h);
        Qs[r*SQ + h]     = v.x;
        Qs[r*SQ + h + 1] = v.y;
        Qs[r*SQ + h + 2] = v.z;
        Qs[r*SQ + h + 3] = v.w;
    }
    if (tid < 64) Lsm[tid] = 0.f;

    float O[4][8];
#pragma unroll
    for (int i = 0; i < 4; i++)
#pragma unroll
        for (int j = 0; j < 8; j++) O[i][j] = 0.f;

    __syncthreads();

    const float inv_cap = 1.0f / SOFTCAP;
    for (int st = 0; st <= qt; st++) {
#pragma unroll
        for (int it = 0; it < 8; it++) {
            int idx = tid + it * 256;
            int r = idx >> 5;
            int h = (idx & 31) << 2;
            size_t gro = ((size_t)(b*Tt + st*64 + r) * Kh + kvh) * Hh + h;
            float4 kv = *(const float4*)(g_K + gro);
            Ks[r*SQ + h]     = kv.x;
            Ks[r*SQ + h + 1] = kv.y;
            Ks[r*SQ + h + 2] = kv.z;
            Ks[r*SQ + h + 3] = kv.w;
            *(float4*)(Vs + r*SV + h) = *(const float4*)(g_V + gro);
        }
        __syncthreads();

        float s[4][4];
#pragma unroll
        for (int i = 0; i < 4; i++)
#pragma unroll
            for (int j = 0; j < 4; j++) s[i][j] = 0.f;
#pragma unroll 4
        for (int kk = 0; kk < 128; kk++) {
            float a[4], bb[4];
#pragma unroll
            for (int i = 0; i < 4; i++) a[i]  = Qs[(r0  + i)*SQ + kk];
#pragma unroll
            for (int j = 0; j < 4; j++) bb[j] = Ks[(c0s + j)*SQ + kk];
#pragma unroll
            for (int i = 0; i < 4; i++)
#pragma unroll
                for (int j = 0; j < 4; j++)
                    s[i][j] = fmaf(a[i], bb[j], s[i][j]);
        }

        const bool diag = (st == qt);
        float rsum[4] = {0.f, 0.f, 0.f, 0.f};
#pragma unroll
        for (int i = 0; i < 4; i++) {
#pragma unroll
            for (int j = 0; j < 4; j++) {
                float v = tanhf(s[i][j] * inv_cap) * SOFTCAP;
                float p = (diag && (c0s + j > r0 + i)) ? 0.f : expf(v - SOFTCAP);
                Ps[(r0 + i)*SP + c0s + j] = p;
                rsum[i] += p;
            }
            psum[(r0 + i)*17 + tx] = rsum[i];
        }
        __syncthreads();

        if (tid < 64) {
            float a = 0.f;
#pragma unroll
            for (int xx = 0; xx < 16; xx++) a += psum[tid*17 + xx];
            Lsm[tid] += a;
        }

#pragma unroll 2
        for (int ss = 0; ss < 64; ss++) {
            float p[4];
#pragma unroll
            for (int i = 0; i < 4; i++) p[i] = Ps[(r0 + i)*SP + ss];
            float4 v0 = *(const float4*)(Vs + ss*SV + c0o);
            float4 v1 = *(const float4*)(Vs + ss*SV + c0o + 4);
#pragma unroll
            for (int i = 0; i < 4; i++) {
                O[i][0] = fmaf(p[i], v0.x, O[i][0]);
                O[i][1] = fmaf(p[i], v0.y, O[i][1]);
                O[i][2] = fmaf(p[i], v0.z, O[i][2]);
                O[i][3] = fmaf(p[i], v0.w, O[i][3]);
                O[i][4] = fmaf(p[i], v1.x, O[i][4]);
                O[i][5] = fmaf(p[i], v1.y, O[i][5]);
                O[i][6] = fmaf(p[i], v1.z, O[i][6]);
                O[i][7] = fmaf(p[i], v1.w, O[i][7]);
            }
        }
        __syncthreads();
    }

#pragma unroll
    for (int i = 0; i < 4; i++) {
        float inv = 1.f / Lsm[r0 + i];
        size_t o = ((size_t)(b*Tt + qt*64 + r0 + i) * Nn + n) * Hh + c0o;
#pragma unroll
        for (int j = 0; j < 8; j++)
            g_E[o + j] = O[i][j] * inv;
    }
}

__global__ void outproj_slow(const float* __restrict__ w_out,
                             float* __restrict__ out) {
    if (g_fastok == 1) return;
    __shared__ float As[16][132];
    __shared__ float Bs[16][128];
    const int j0 = blockIdx.x * 128;
    const int m0 = blockIdx.y * 128;
    const int tid = threadIdx.x;
    const int ty = tid >> 4, tx = tid & 15;
    float acc[8][8];
#pragma unroll
    for (int i = 0; i < 8; i++)
#pragma unroll
        for (int j = 0; j < 8; j++) acc[i][j] = 0.f;
    for (int k0 = 0; k0 < Nn*Hh; k0 += 16) {
#pragma unroll
        for (int it = 0; it < 2; it++) {
            int idx = tid + it * 256;
            int r  = idx >> 2;
            int c4 = (idx & 3) << 2;
            float4 v = *(const float4*)(g_E + (size_t)(m0 + r) * (Nn*Hh) + k0 + c4);
            As[c4+0][r] = v.x; As[c4+1][r] = v.y;
            As[c4+2][r] = v.z; As[c4+3][r] = v.w;
        }
#pragma unroll
        for (int it = 0; it < 2; it++) {
            int idx = tid + it * 256;
            int kk = idx >> 5;
            int j4 = (idx & 31) << 2;
            *(float4*)(&Bs[kk][j4]) = *(const float4*)(w_out + (size_t)(k0 + kk) * Dd + j0 + j4);
        }
        __syncthreads();
#pragma unroll
        for (int kk = 0; kk < 16; kk++) {
            float a[8], bfr[8];
#pragma unroll
            for (int i = 0; i < 8; i++) a[i] = As[kk][ty*8 + i];
#pragma unroll
            for (int j = 0; j < 8; j++) bfr[j] = Bs[kk][tx*8 + j];
#pragma unroll
            for (int i = 0; i < 8; i++)
#pragma unroll
                for (int j = 0; j < 8; j++)
                    acc[i][j] = fmaf(a[i], bfr[j], acc[i][j]);
        }
        __syncthreads();
    }
#pragma unroll
    for (int i = 0; i < 8; i++) {
        size_t m = (size_t)(m0 + ty*8 + i);
#pragma unroll
        for (int j = 0; j < 8; j++)
            out[m * Dd + j0 + tx*8 + j] = acc[i][j];
    }
}

// ---------------------------------------------------------------------------
extern "C" void kernel_launch(void* const* d_in, const int* in_sizes, int n_in,
                              void* d_out, int out_size) {
    const float* x     = (const float*)d_in[0];
    const int*   pos   = (const int*)  d_in[1];
    // d_in[2] = attn_mask (causal; handled analytically)
    const float* w_q   = (const float*)d_in[3];
    const float* w_kv  = (const float*)d_in[4];
    const float* w_out = (const float*)d_in[5];
    float* out = (float*)d_out;

    probe_kernel<<<1, 32>>>(x);
    roundx_kernel<<<(Mrows*Dd/4 + 255)/256, 256>>>(x);
    transpose_kernel<<<dim3(64, 128, 2), dim3(32, 8)>>>(w_q, w_kv, w_out);

    cudaFuncSetAttribute(gemm_mma_kernel,
                         cudaFuncAttributeMaxDynamicSharedMemorySize, GEMM_SMEM);
    gemm_mma_kernel<<<dim3(16, 32), 256, GEMM_SMEM>>>(nullptr, 0);
    proj_slow<<<dim3(32, 32), 256>>>(x, w_q, w_kv);

    {
        int total = Mrows*Nn*64 + Mrows*Kh*64;
        rope_kernel<<<(total + 255) / 256, 256>>>(pos);
    }

    cudaFuncSetAttribute(attn_fast,
                         cudaFuncAttributeMaxDynamicSharedMemorySize, ATTN_SMEM_F);
    attn_fast<<<dim3(32, 16, 2), 256, ATTN_SMEM_F>>>();
    cudaFuncSetAttribute(attn_slow,
                         cudaFuncAttributeMaxDynamicSharedMemorySize, ATTN_SMEM_S);
    attn_slow<<<dim3(32, 16, 2), 256, ATTN_SMEM_S>>>();

    gemm_mma_kernel<<<dim3(8, 32), 256, GEMM_SMEM>>>(out, 1);
    outproj_slow<<<dim3(16, 32), 256>>>(w_out, out);
}

// round 7
// speedup vs baseline: 3.5804x; 1.1432x over previous
#include <cuda_runtime.h>
#include <math.h>
#include <stdint.h>

// Problem constants
#define Bb 2
#define Tt 2048
#define Dd 2048
#define Nn 16
#define Kh 8
#define Hh 128
#define Mrows (Bb*Tt)
#define SOFTCAP 50.0f

// Scratch (no cudaMalloc allowed)
__device__ float g_X32[(size_t)Mrows*Dd];      // x rounded to tf32
__device__ float g_Q[(size_t)Mrows*Nn*Hh];     // [M, 2048]  (tf32 after rope)
__device__ float g_K[(size_t)Mrows*Kh*Hh];     // [M, 1024]  (tf32 after rope)
__device__ float g_V[(size_t)Mrows*Kh*Hh];     // [M, 1024]  (tf32 from gemm epilogue)
__device__ float g_E[(size_t)Mrows*Nn*Hh];     // encoded (tf32)
__device__ float g_Wt[(size_t)4096*2048];      // W_qkv^T (tf32)
__device__ float g_Wot[(size_t)2048*2048];     // w_out^T (tf32)

// ---------------------------------------------------------------------------
// Helpers
// ---------------------------------------------------------------------------
__device__ __forceinline__ uint32_t smem_to_u32(const void* p) {
    uint32_t a;
    asm("{ .reg .u64 t; cvta.to.shared.u64 t, %1; cvt.u32.u64 %0, t; }" : "=r"(a) : "l"(p));
    return a;
}
__device__ __forceinline__ float to_tf32(float x) {
    float r;
    asm("cvt.rna.tf32.f32 %0, %1;" : "=f"(r) : "f"(x));
    return r;
}
__device__ __forceinline__ void mma_tf32(float d[4], const uint32_t a[4], const uint32_t b[2]) {
    asm volatile(
        "mma.sync.aligned.m16n8k8.row.col.f32.tf32.tf32.f32 "
        "{%0,%1,%2,%3}, {%4,%5,%6,%7}, {%8,%9}, {%0,%1,%2,%3};"
        : "+f"(d[0]), "+f"(d[1]), "+f"(d[2]), "+f"(d[3])
        : "r"(a[0]), "r"(a[1]), "r"(a[2]), "r"(a[3]), "r"(b[0]), "r"(b[1]));
}
#define CP_ASYNC16(dst, src) \
    asm volatile("cp.async.cg.shared.global [%0], [%1], 16;" :: "r"(dst), "l"(src) : "memory")
#define CP_COMMIT() asm volatile("cp.async.commit_group;" ::: "memory")
#define CP_WAIT1()  asm volatile("cp.async.wait_group 1;" ::: "memory")
#define CP_WAIT0()  asm volatile("cp.async.wait_group 0;" ::: "memory")
#define FU(x) __float_as_uint(x)

// exp(50*tanh(x/50) - 50)  ==  exp2( -144.2695.../ (exp2(x*0.0577078...) + 1) )
__device__ __forceinline__ float softcap_exp(float x) {
    float w = exp2f(x * 0.057707801635559011f);     // e^(x/25) via ex2
    return exp2f(__fdividef(-144.26950408889634f, w + 1.0f));
}

// ---------------------------------------------------------------------------
// Prep kernels
// ---------------------------------------------------------------------------
__global__ void roundx_kernel(const float* __restrict__ x) {
    size_t i = ((size_t)blockIdx.x * blockDim.x + threadIdx.x) * 4;
    float4 v = *(const float4*)(x + i);
    v.x = to_tf32(v.x); v.y = to_tf32(v.y); v.z = to_tf32(v.z); v.w = to_tf32(v.w);
    *(float4*)(g_X32 + i) = v;
}

__global__ void transpose_kernel(const float* __restrict__ w_q,
                                 const float* __restrict__ w_kv,
                                 const float* __restrict__ w_out) {
    __shared__ float t[32][33];
    const int tx = threadIdx.x, ty = threadIdx.y;   // 32 x 8
    const int bx = blockIdx.x, by = blockIdx.y;
    if (blockIdx.z == 0) {
        const int j0 = by * 32, d0 = bx * 32;
        const int j = j0 + tx;
        const int h = j & 127, hd = j >> 7;
        const float* src;
        if (hd < 16)      src = w_q  + (size_t)hd * 2048 * 128 + h;
        else if (hd < 24) src = w_kv + (size_t)(hd - 16) * 2048 * 128 + h;
        else              src = w_kv + (size_t)8 * 2048 * 128 + (size_t)(hd - 24) * 2048 * 128 + h;
#pragma unroll
        for (int i = 0; i < 4; i++) {
            int d = d0 + ty + i * 8;
            t[tx][ty + i * 8] = to_tf32(src[(size_t)d * 128]);
        }
        __syncthreads();
#pragma unroll
        for (int i = 0; i < 4; i++) {
            int jj = j0 + ty + i * 8;
            g_Wt[(size_t)jj * 2048 + d0 + tx] = t[ty + i * 8][tx];
        }
    } else {
        if (by >= 64) return;
        const int k0 = by * 32, d0 = bx * 32;
#pragma unroll
        for (int i = 0; i < 4; i++) {
            int k = k0 + ty + i * 8;
            t[ty + i * 8][tx] = to_tf32(w_out[(size_t)k * 2048 + d0 + tx]);
        }
        __syncthreads();
#pragma unroll
        for (int i = 0; i < 4; i++) {
            int d = d0 + ty + i * 8;
            g_Wot[(size_t)d * 2048 + k0 + tx] = t[tx][ty + i * 8];
        }
    }
}

// ---------------------------------------------------------------------------
// tf32 mma GEMM, CTA 128x256, warp 64x64, K-chunk 32, 3-stage cp.async,
// ONE barrier per chunk, prefetch-before-compute.
//   mode 0: C = g_X32 @ g_Wt^T  -> split g_Q/g_K/g_V  (V rounded to tf32)
//   mode 1: C = g_E  @ g_Wot^T  -> outp
// ---------------------------------------------------------------------------
#define GP 36
#define STAGE_FLOATS (128*GP + 256*GP)    // 13824 floats = 55296 B
#define GEMM_SMEM (3*STAGE_FLOATS*4)      // 165888 B

__global__ __launch_bounds__(256, 1)
void gemm_mma_kernel(float* __restrict__ outp, int mode) {
    const float* A  = (mode == 0) ? g_X32 : g_E;
    const float* Bt = (mode == 0) ? g_Wt  : g_Wot;
    extern __shared__ float smf[];
    const uint32_t smem_base = smem_to_u32(smf);
    const int tid = threadIdx.x;
    const int lane = tid & 31;
    const int wid = tid >> 5;
    const int g = lane >> 2, t4 = lane & 3;
    const int wm = wid & 1, wn = wid >> 1;
    const int m0 = blockIdx.y * 128;
    const int jg = blockIdx.x * 256;

    float c[4][8][4];
#pragma unroll
    for (int mt = 0; mt < 4; mt++)
#pragma unroll
        for (int nt = 0; nt < 8; nt++)
#pragma unroll
            for (int q = 0; q < 4; q++) c[mt][nt][q] = 0.f;

    auto issue = [&](int kt, int stage) {
        const int k0 = kt * 32;
        const uint32_t sbA = smem_base + stage * (STAGE_FLOATS * 4);
        const uint32_t sbB = sbA + 128 * GP * 4;
#pragma unroll
        for (int i = 0; i < 4; i++) {
            int ch = tid + i * 256;
            int r = ch >> 3, cc = (ch & 7) << 2;
            CP_ASYNC16(sbA + (uint32_t)(r * GP + cc) * 4,
                       A + (size_t)(m0 + r) * 2048 + k0 + cc);
        }
#pragma unroll
        for (int i = 0; i < 8; i++) {
            int ch = tid + i * 256;
            int r = ch >> 3, cc = (ch & 7) << 2;
            CP_ASYNC16(sbB + (uint32_t)(r * GP + cc) * 4,
                       Bt + (size_t)(jg + r) * 2048 + k0 + cc);
        }
    };

    issue(0, 0); CP_COMMIT();
    issue(1, 1); CP_COMMIT();

    for (int kt = 0; kt < 64; kt++) {
        if (kt < 63) CP_WAIT1(); else CP_WAIT0();
        __syncthreads();
        if (kt + 2 < 64) { issue(kt + 2, (kt + 2) % 3); CP_COMMIT(); }
        const float* as = smf + (kt % 3) * STAGE_FLOATS;
        const float* bs = as + 128 * GP;
#pragma unroll
        for (int ks = 0; ks < 4; ks++) {
            const int k = ks * 8;
            uint32_t a[4][4];
#pragma unroll
            for (int mt = 0; mt < 4; mt++) {
                const float* ap = as + (wm * 64 + mt * 16 + g) * GP + k + t4;
                a[mt][0] = FU(ap[0]);
                a[mt][1] = FU(ap[8 * GP]);
                a[mt][2] = FU(ap[4]);
                a[mt][3] = FU(ap[8 * GP + 4]);
            }
#pragma unroll
            for (int nt = 0; nt < 8; nt++) {
                const float* bp = bs + (wn * 64 + nt * 8 + g) * GP + k + t4;
                uint32_t b[2] = {FU(bp[0]), FU(bp[4])};
#pragma unroll
                for (int mt = 0; mt < 4; mt++)
                    mma_tf32(c[mt][nt], a[mt], b);
            }
        }
    }

    float* obase; int ostride; bool roundv = false;
    if (mode == 0) {
        if (jg < 2048)      { obase = g_Q + jg;        ostride = 2048; }
        else if (jg < 3072) { obase = g_K + (jg-2048); ostride = 1024; }
        else                { obase = g_V + (jg-3072); ostride = 1024; roundv = true; }
    } else { obase = outp + jg; ostride = 2048; }
#pragma unroll
    for (int mt = 0; mt < 4; mt++) {
        int r0 = m0 + wm * 64 + mt * 16 + g;
#pragma unroll
        for (int nt = 0; nt < 8; nt++) {
            int col = wn * 64 + nt * 8 + 2 * t4;
            float v0 = c[mt][nt][0], v1 = c[mt][nt][1];
            float v2 = c[mt][nt][2], v3 = c[mt][nt][3];
            if (roundv) { v0 = to_tf32(v0); v1 = to_tf32(v1); v2 = to_tf32(v2); v3 = to_tf32(v3); }
            *(float2*)(obase + (size_t)r0 * ostride + col)       = make_float2(v0, v1);
            *(float2*)(obase + (size_t)(r0 + 8) * ostride + col) = make_float2(v2, v3);
        }
    }
}

// ---------------------------------------------------------------------------
// RoPE on Q (with 1/sqrt(H) scale) and K; outputs tf32-rounded.
// ---------------------------------------------------------------------------
__global__ void rope_kernel(const int* __restrict__ positions) {
    const int totalQ = Mrows * Nn * 64;
    const int totalK = Mrows * Kh * 64;
    int idx = blockIdx.x * blockDim.x + threadIdx.x;
    if (idx < totalQ) {
        int m   = idx / (Nn * 64);
        int rem = idx % (Nn * 64);
        int n = rem >> 6;
        int i = rem & 63;
        float pos = (float)positions[m];
        float inv_ts = exp2f(-13.287712379549449f * ((float)i * 0.015625f));
        float s, c;
        sincosf(pos * inv_ts, &s, &c);
        float* base = g_Q + (size_t)m * (Nn*Hh) + n * Hh;
        float f = base[i], sec = base[i + 64];
        const float sc = 0.08838834764831845f;
        base[i]      = to_tf32((f * c - sec * s) * sc);
        base[i + 64] = to_tf32((sec * c + f * s) * sc);
    } else {
        int id2 = idx - totalQ;
        if (id2 >= totalK) return;
        int m   = id2 / (Kh * 64);
        int rem = id2 % (Kh * 64);
        int n = rem >> 6;
        int i = rem & 63;
        float pos = (float)positions[m];
        float inv_ts = exp2f(-13.287712379549449f * ((float)i * 0.015625f));
        float s, c;
        sincosf(pos * inv_ts, &s, &c);
        float* base = g_K + (size_t)m * (Kh*Hh) + n * Hh;
        float f = base[i], sec = base[i + 64];
        base[i]      = to_tf32(f * c - sec * s);
        base[i + 64] = to_tf32(sec * c + f * s);
    }
}

// ---------------------------------------------------------------------------
// Attention v2.1: q-tile 128, k-tile 64, 8 warps.
// S phase: warp = 32-row band (wid&3) x 32-col half (wid>>2).
// PV phase: warp = 32-row band x 64-col half (ch = wid>>2) of the 128-wide O.
// K double-buffered via cp.async; V single-buffered, hidden behind S-mma.
// Fixed-max softmax p = exp(50 tanh(s/50) - 50) via 3-MUFU identity.
// ---------------------------------------------------------------------------
#define AQ 132
#define AP 68
#define ATTN_FLOATS (128*AQ + 3*64*AQ + 128*AP + 256 + 128)
#define ATTN_SMEM (ATTN_FLOATS * 4)   // 205,312 B

__global__ __launch_bounds__(256, 1)
void attn_kernel() {
    extern __shared__ float sm[];
    float* Qs   = sm;                    // [128][AQ]
    float* Kb0  = Qs  + 128*AQ;          // [64][AQ]
    float* Kb1  = Kb0 + 64*AQ;           // [64][AQ]
    float* Vs   = Kb1 + 64*AQ;           // [64][AQ]
    float* Ps   = Vs  + 64*AQ;           // [128][AP]
    float* psum = Ps  + 128*AP;          // [128][2]
    float* Lsm  = psum + 256;            // [128]

    const int qt = 15 - blockIdx.x;      // long CTAs first
    const int n  = blockIdx.y, b = blockIdx.z;
    const int kvh = n >> 1;
    const int tid = threadIdx.x, lane = tid & 31, wid = tid >> 5;
    const int g = lane >> 2, t4 = lane & 3;
    const int rb = (wid & 3) * 32;       // S/O row band
    const int ch = wid >> 2;             // column half index (0/1)
    const int cb = ch * 32;              // S col half
    const int nst = 2 * qt + 2;

    // Q tile load (group 0)
    {
        uint32_t qsm = smem_to_u32(Qs);
        const size_t qbase = ((size_t)(b*Tt + qt*128) * Nn + n) * Hh;
#pragma unroll
        for (int i = 0; i < 16; i++) {
            int idx = tid + i * 256;
            int r = idx >> 5, h = (idx & 31) << 2;
            CP_ASYNC16(qsm + (uint32_t)(r*AQ + h) * 4, g_Q + qbase + (size_t)r * 2048 + h);
        }
        CP_COMMIT();
    }
    // K(0) (group 1)
    {
        uint32_t ks = smem_to_u32(Kb0);
        const size_t base = ((size_t)(b*Tt) * Kh + kvh) * Hh;
#pragma unroll
        for (int i = 0; i < 8; i++) {
            int idx = tid + i * 256;
            int r = idx >> 5, h = (idx & 31) << 2;
            CP_ASYNC16(ks + (uint32_t)(r*AQ + h) * 4, g_K + base + (size_t)r * 1024 + h);
        }
        CP_COMMIT();
    }

    if (tid < 128) Lsm[tid] = 0.f;

    float o[2][8][4];
#pragma unroll
    for (int mt = 0; mt < 2; mt++)
#pragma unroll
        for (int nt = 0; nt < 8; nt++)
#pragma unroll
            for (int q = 0; q < 4; q++) o[mt][nt][q] = 0.f;

    for (int st = 0; st < nst; st++) {
        const float* Kc = (st & 1) ? Kb1 : Kb0;
        // issue V(st)
        {
            uint32_t vs = smem_to_u32(Vs);
            const size_t base = ((size_t)(b*Tt + st*64) * Kh + kvh) * Hh;
#pragma unroll
            for (int i = 0; i < 8; i++) {
                int idx = tid + i * 256;
                int r = idx >> 5, h = (idx & 31) << 2;
                CP_ASYNC16(vs + (uint32_t)(r*AQ + h) * 4, g_V + base + (size_t)r * 1024 + h);
            }
            CP_COMMIT();
        }
        CP_WAIT1();                    // K(st) (and Q) ready
        __syncthreads();

        // ---- S = Q Kc^T : warp 32x32 ----
        float s[2][4][4];
#pragma unroll
        for (int mt = 0; mt < 2; mt++)
#pragma unroll
            for (int nt = 0; nt < 4; nt++)
#pragma unroll
                for (int q = 0; q < 4; q++) s[mt][nt][q] = 0.f;
#pragma unroll
        for (int ks = 0; ks < 16; ks++) {
            const int k = ks * 8;
            uint32_t a[2][4];
#pragma unroll
            for (int mt = 0; mt < 2; mt++) {
                const float* ap = Qs + (rb + mt*16 + g) * AQ + k + t4;
                a[mt][0] = FU(ap[0]);
                a[mt][1] = FU(ap[8*AQ]);
                a[mt][2] = FU(ap[4]);
                a[mt][3] = FU(ap[8*AQ + 4]);
            }
#pragma unroll
            for (int nt = 0; nt < 4; nt++) {
                const float* bp = Kc + (cb + nt*8 + g) * AQ + k + t4;
                uint32_t bb[2] = {FU(bp[0]), FU(bp[4])};
#pragma unroll
                for (int mt = 0; mt < 2; mt++)
                    mma_tf32(s[mt][nt], a[mt], bb);
            }
        }

        // issue K(st+1) into other buffer
        if (st + 1 < nst) {
            uint32_t ks = smem_to_u32((st & 1) ? Kb0 : Kb1);
            const size_t base = ((size_t)(b*Tt + (st+1)*64) * Kh + kvh) * Hh;
#pragma unroll
            for (int i = 0; i < 8; i++) {
                int idx = tid + i * 256;
                int r = idx >> 5, h = (idx & 31) << 2;
                CP_ASYNC16(ks + (uint32_t)(r*AQ + h) * 4, g_K + base + (size_t)r * 1024 + h);
            }
            CP_COMMIT();
            CP_WAIT1();                // V(st) ready (only K(st+1) pending)
        } else {
            CP_WAIT0();
        }
        __syncthreads();

        // ---- softcap + causal mask + exp; P + row sums ----
        const int grow0 = qt*128 + rb;
        float rs[4] = {0.f, 0.f, 0.f, 0.f};
#pragma unroll
        for (int mt = 0; mt < 2; mt++) {
            const int rlo = rb + mt*16 + g, rhi = rlo + 8;
            const int grlo = grow0 + mt*16 + g, grhi = grlo + 8;
#pragma unroll
            for (int nt = 0; nt < 4; nt++) {
                const int cc = cb + nt*8 + 2*t4;
                const int gc = st*64 + cc;
                float p00 = softcap_exp(s[mt][nt][0]);
                float p01 = softcap_exp(s[mt][nt][1]);
                float p10 = softcap_exp(s[mt][nt][2]);
                float p11 = softcap_exp(s[mt][nt][3]);
                if (gc     > grlo) p00 = 0.f;
                if (gc + 1 > grlo) p01 = 0.f;
                if (gc     > grhi) p10 = 0.f;
                if (gc + 1 > grhi) p11 = 0.f;
                p00 = to_tf32(p00); p01 = to_tf32(p01);
                p10 = to_tf32(p10); p11 = to_tf32(p11);
                *(float2*)(Ps + rlo*AP + cc) = make_float2(p00, p01);
                *(float2*)(Ps + rhi*AP + cc) = make_float2(p10, p11);
                rs[2*mt]   += p00 + p01;
                rs[2*mt+1] += p10 + p11;
            }
        }
#pragma unroll
        for (int q = 0; q < 4; q++) {
            rs[q] += __shfl_xor_sync(0xffffffffu, rs[q], 1);
            rs[q] += __shfl_xor_sync(0xffffffffu, rs[q], 2);
        }
        if (t4 == 0) {
#pragma unroll
            for (int mt = 0; mt < 2; mt++) {
                psum[(rb + mt*16 + g)     * 2 + ch] = rs[2*mt];
                psum[(rb + mt*16 + g + 8) * 2 + ch] = rs[2*mt+1];
            }
        }
        __syncthreads();
        if (tid < 128) Lsm[tid] += psum[tid*2] + psum[tid*2 + 1];

        // ---- O += P V : warp 32 rows x 64-col half (ch) ----
#pragma unroll
        for (int ks = 0; ks < 8; ks++) {
            const int k = ks * 8;
            uint32_t a[2][4];
#pragma unroll
            for (int mt = 0; mt < 2; mt++) {
                const float* ap = Ps + (rb + mt*16 + g) * AP + k + t4;
                a[mt][0] = FU(ap[0]);
                a[mt][1] = FU(ap[8*AP]);
                a[mt][2] = FU(ap[4]);
                a[mt][3] = FU(ap[8*AP + 4]);
            }
#pragma unroll
            for (int nt = 0; nt < 8; nt++) {
                const float* bp = Vs + (k + t4) * AQ + ch*64 + nt*8 + g;
                uint32_t bb[2] = {FU(bp[0]), FU(bp[4*AQ])};
#pragma unroll
                for (int mt = 0; mt < 2; mt++)
                    mma_tf32(o[mt][nt], a[mt], bb);
            }
        }
        __syncthreads();   // protect Vs/Ps before next iter's overwrite
    }

    // ---- normalize + write encoded (tf32) ----
#pragma unroll
    for (int mt = 0; mt < 2; mt++) {
        const int rlo = rb + mt*16 + g, rhi = rlo + 8;
        const float invlo = 1.f / Lsm[rlo];
        const float invhi = 1.f / Lsm[rhi];
        const size_t blo = ((size_t)(b*Tt + qt*128 + rlo) * Nn + n) * Hh;
        const size_t bhi = ((size_t)(b*Tt + qt*128 + rhi) * Nn + n) * Hh;
#pragma unroll
        for (int nt = 0; nt < 8; nt++) {
            const int col = ch*64 + nt*8 + 2*t4;
            *(float2*)(g_E + blo + col) =
                make_float2(to_tf32(o[mt][nt][0]*invlo), to_tf32(o[mt][nt][1]*invlo));
            *(float2*)(g_E + bhi + col) =
                make_float2(to_tf32(o[mt][nt][2]*invhi), to_tf32(o[mt][nt][3]*invhi));
        }
    }
}

// ---------------------------------------------------------------------------
extern "C" void kernel_launch(void* const* d_in, const int* in_sizes, int n_in,
                              void* d_out, int out_size) {
    const float* x     = (const float*)d_in[0];
    const int*   pos   = (const int*)  d_in[1];
    // d_in[2] = attn_mask (causal; handled analytically)
    const float* w_q   = (const float*)d_in[3];
    const float* w_kv  = (const float*)d_in[4];
    const float* w_out = (const float*)d_in[5];
    float* out = (float*)d_out;

    roundx_kernel<<<(Mrows*Dd/4 + 255)/256, 256>>>(x);
    transpose_kernel<<<dim3(64, 128, 2), dim3(32, 8)>>>(w_q, w_kv, w_out);

    cudaFuncSetAttribute(gemm_mma_kernel,
                         cudaFuncAttributeMaxDynamicSharedMemorySize, GEMM_SMEM);
    gemm_mma_kernel<<<dim3(16, 32), 256, GEMM_SMEM>>>(nullptr, 0);

    {
        int total = Mrows*Nn*64 + Mrows*Kh*64;
        rope_kernel<<<(total + 255) / 256, 256>>>(pos);
    }

    cudaFuncSetAttribute(attn_kernel,
                         cudaFuncAttributeMaxDynamicSharedMemorySize, ATTN_SMEM);
    attn_kernel<<<dim3(16, 16, 2), 256, ATTN_SMEM>>>();

    gemm_mma_kernel<<<dim3(8, 32), 256, GEMM_SMEM>>>(out, 1);
}